// round 5
// baseline (speedup 1.0000x reference)
#include <cuda_runtime.h>

// ---------------------------------------------------------------------------
// Fully-fused 2-layer GAT attention. 512 CTAs x 320 threads, 4 CTAs/SM
// (40 warps/SM, single wave on 148 SMs).
//   exp(leaky_relu(q+k)) = Fq * Ek * max(e^{0.99q}, e^{-0.99k}); Fq cancels.
//   X <- Ek*X;  ATT[i] = sum_j max(Hq,Gk)*EkX / sum_j max(Hq,Gk)*Ek
// 10 warps x 5 rows = exactly 50 rows: no guards anywhere.
// ---------------------------------------------------------------------------

#define TPB 320
typedef unsigned long long u64;

constexpr int Bn = 512, Nn = 50, Dn = 64;
constexpr int NW = 10;                        // warps per CTA
constexpr int ASZ = Nn * Dn;                  // 3200
constexpr int EMB_STRIDE = (Nn + 1) * Dn;     // 3264

// shared layout (floats)
constexpr int O_X    = 0;          // x -> EkX1 -> av1 -> EkX2
constexpr int O_HQ   = ASZ;        // Hq -> ATT
constexpr int O_EKGK = 2 * ASZ;    // rows of 128: {ek0,ek1,gk0,gk1} per d-pair
constexpr int O_BA1  = 4 * ASZ;
constexpr int O_BA2  = O_BA1 + Dn;
constexpr int O_B1   = O_BA2 + Dn;
constexpr int O_B2   = O_B1 + Dn;
constexpr int O_E0   = O_B2 + Dn;
constexpr int SMEM_FLOATS = O_E0 + Dn;        // 13120 floats = 52480 B

// ---- f32x2 helpers --------------------------------------------------------
__device__ __forceinline__ u64 pk2(float lo, float hi) {
    u64 r; asm("mov.b64 %0, {%1,%2};" : "=l"(r) : "f"(lo), "f"(hi)); return r;
}
__device__ __forceinline__ u64 dup2(float x) {
    u64 r; asm("mov.b64 %0, {%1,%1};" : "=l"(r) : "f"(x)); return r;
}
__device__ __forceinline__ float lo32(u64 v) {
    float a, b; asm("mov.b64 {%0,%1}, %2;" : "=f"(a), "=f"(b) : "l"(v)); return a;
}
__device__ __forceinline__ float hi32(u64 v) {
    float a, b; asm("mov.b64 {%0,%1}, %2;" : "=f"(a), "=f"(b) : "l"(v)); return b;
}
__device__ __forceinline__ u64 fma2(u64 a, u64 b, u64 c) {
    u64 d; asm("fma.rn.f32x2 %0, %1, %2, %3;" : "=l"(d) : "l"(a), "l"(b), "l"(c)); return d;
}
__device__ __forceinline__ u64 mul2(u64 a, u64 b) {
    u64 d; asm("mul.rn.f32x2 %0, %1, %2;" : "=l"(d) : "l"(a), "l"(b)); return d;
}
__device__ __forceinline__ u64 max2(u64 a, u64 b) {
    float al, ah, bl, bh;
    asm("mov.b64 {%0,%1}, %2;" : "=f"(al), "=f"(ah) : "l"(a));
    asm("mov.b64 {%0,%1}, %2;" : "=f"(bl), "=f"(bh) : "l"(b));
    return pk2(fmaxf(al, bl), fmaxf(ah, bh));
}

// ---- qk: q=X@Wa1+ba1, k=X@Wa2+ba2 -> HQ, EK|GK; then X <- Ek*X -------------
__device__ __forceinline__ void qk_phase(float* sm, const float* __restrict__ Wa1,
                                         const float* __restrict__ Wa2) {
    const int tid = threadIdx.x, lane = tid & 31, w = tid >> 5;
    const int d2 = lane * 2;

    u64 aq[5], ak[5];
    const u64 bq = *reinterpret_cast<const u64*>(sm + O_BA1 + d2);
    const u64 bk = *reinterpret_cast<const u64*>(sm + O_BA2 + d2);
#pragma unroll
    for (int r = 0; r < 5; ++r) { aq[r] = bq; ak[r] = bk; }

#pragma unroll 2
    for (int c0 = 0; c0 < Dn; c0 += 2) {
        u64 x2[5];
#pragma unroll
        for (int r = 0; r < 5; ++r)
            x2[r] = *reinterpret_cast<const u64*>(sm + O_X + (w + NW * r) * Dn + c0);
#pragma unroll
        for (int u = 0; u < 2; ++u) {
            const u64 wa = __ldg(reinterpret_cast<const u64*>(Wa1 + (c0 + u) * Dn) + lane);
            const u64 wb = __ldg(reinterpret_cast<const u64*>(Wa2 + (c0 + u) * Dn) + lane);
#pragma unroll
            for (int r = 0; r < 5; ++r) {
                const u64 xx = dup2(u ? hi32(x2[r]) : lo32(x2[r]));
                aq[r] = fma2(xx, wa, aq[r]);
                ak[r] = fma2(xx, wb, ak[r]);
            }
        }
    }

    u64 ekr[5];
#pragma unroll
    for (int r = 0; r < 5; ++r) {
        const int row = w + NW * r;
        const float qa = lo32(aq[r]), qb = hi32(aq[r]);
        const float ka = lo32(ak[r]), kb = hi32(ak[r]);
        *reinterpret_cast<u64*>(sm + O_HQ + row * Dn + d2) =
            pk2(__expf(0.99f * qa), __expf(0.99f * qb));
        const float e0 = __expf(ka), e1 = __expf(kb);
        ekr[r] = pk2(e0, e1);
        *reinterpret_cast<float4*>(sm + O_EKGK + row * 2 * Dn + d2 * 2) =
            make_float4(e0, e1, __expf(-0.99f * ka), __expf(-0.99f * kb));
    }
    __syncwarp();   // rows warp-private: only intra-warp hazard on X
#pragma unroll
    for (int r = 0; r < 5; ++r) {
        u64* px = reinterpret_cast<u64*>(sm + O_X + (w + NW * r) * Dn + d2);
        *px = mul2(ekr[r], *px);   // X <- Ek * X
    }
}

// ---- attention: ATT[i] = sum_j m*EkX / sum_j m*Ek, m = max(Hq_i, Gk_j) -----
__device__ __forceinline__ void att_phase(float* sm) {
    const int tid = threadIdx.x;
    const int d2 = (tid & 31) * 2;
    const int g = tid >> 5;

    u64 hq[5], num[5], den[5];
#pragma unroll
    for (int r = 0; r < 5; ++r) {
        hq[r] = *reinterpret_cast<const u64*>(sm + O_HQ + (g + NW * r) * Dn + d2);
        num[r] = 0ull; den[r] = 0ull;
    }
#pragma unroll 2
    for (int j = 0; j < Nn; ++j) {
        const float4 eg = *reinterpret_cast<const float4*>(sm + O_EKGK + j * 2 * Dn + d2 * 2);
        const u64 ek = pk2(eg.x, eg.y);
        const u64 gk = pk2(eg.z, eg.w);
        const u64 xw = *reinterpret_cast<const u64*>(sm + O_X + j * Dn + d2);
#pragma unroll
        for (int r = 0; r < 5; ++r) {
            const u64 m = max2(hq[r], gk);
            den[r] = fma2(m, ek, den[r]);
            num[r] = fma2(m, xw, num[r]);
        }
    }
#pragma unroll
    for (int r = 0; r < 5; ++r) {
        *reinterpret_cast<u64*>(sm + O_HQ + (g + NW * r) * Dn + d2) =
            pk2(__fdividef(lo32(num[r]), lo32(den[r])),
                __fdividef(hi32(num[r]), hi32(den[r])));
    }
}

// ---- gemm: ATT @ W + b. FINAL=false -> X (av1). FINAL=true -> gmem out -----
template <bool FINAL>
__device__ __forceinline__ void gemm_phase(float* sm, const float* __restrict__ W,
                                           int bofs, const float* __restrict__ emb,
                                           float* __restrict__ out, int b) {
    const int tid = threadIdx.x, lane = tid & 31, w = tid >> 5;
    const int d2 = lane * 2;

    u64 acc[5];
    const u64 bb = *reinterpret_cast<const u64*>(sm + bofs + d2);
#pragma unroll
    for (int r = 0; r < 5; ++r) acc[r] = bb;

#pragma unroll 2
    for (int c0 = 0; c0 < Dn; c0 += 2) {
        u64 x2[5];
#pragma unroll
        for (int r = 0; r < 5; ++r)
            x2[r] = *reinterpret_cast<const u64*>(sm + O_HQ + (w + NW * r) * Dn + c0);
#pragma unroll
        for (int u = 0; u < 2; ++u) {
            const u64 wv = __ldg(reinterpret_cast<const u64*>(W + (c0 + u) * Dn) + lane);
#pragma unroll
            for (int r = 0; r < 5; ++r)
                acc[r] = fma2(dup2(u ? hi32(x2[r]) : lo32(x2[r])), wv, acc[r]);
        }
    }
#pragma unroll
    for (int r = 0; r < 5; ++r) {
        const int row = w + NW * r;
        if (!FINAL) {
            *reinterpret_cast<u64*>(sm + O_X + row * Dn + d2) = acc[r];   // av1
        } else {
            const u64 ekx = *reinterpret_cast<const u64*>(sm + O_X + row * Dn + d2);
            const u64 ek  = *reinterpret_cast<const u64*>(sm + O_EKGK + row * 2 * Dn + d2 * 2);
            const float av0 = __fdividef(lo32(ekx), lo32(ek));   // av1 = EkX/Ek
            const float av1 = __fdividef(hi32(ekx), hi32(ek));
            const float e0a = sm[O_E0 + d2], e0b = sm[O_E0 + d2 + 1];
            const float2 ie = __ldg(reinterpret_cast<const float2*>(
                emb + b * EMB_STRIDE + (row + 1) * Dn + d2));
            float r0 = lo32(acc[r]) + av0 + e0a * ie.x;
            float r1 = hi32(acc[r]) + av1 + e0b * ie.y;
            r0 = fmaxf(r0, 0.01f * r0);
            r1 = fmaxf(r1, 0.01f * r1);
            *reinterpret_cast<float2*>(out + b * ASZ + row * Dn + d2) =
                make_float2(r0, r1);
        }
    }
}

__global__ void __launch_bounds__(TPB, 4)
att0_fused_kernel(const float* __restrict__ emb,
                  const float* __restrict__ Wa1, const float* __restrict__ ba1,
                  const float* __restrict__ Wa2, const float* __restrict__ ba2,
                  const float* __restrict__ W1,  const float* __restrict__ b1,
                  const float* __restrict__ W2,  const float* __restrict__ b2,
                  float* __restrict__ out) {
    extern __shared__ float sm[];
    const int b = blockIdx.x, tid = threadIdx.x;
    const float* __restrict__ eb = emb + b * EMB_STRIDE;

    for (int idx = tid; idx < ASZ / 4; idx += TPB)
        reinterpret_cast<float4*>(sm + O_X)[idx] =
            __ldg(reinterpret_cast<const float4*>(eb + Dn) + idx);
    if (tid < Dn) {
        sm[O_BA1 + tid] = ba1[tid];
        sm[O_BA2 + tid] = ba2[tid];
        sm[O_B1  + tid] = b1[tid];
        sm[O_B2  + tid] = b2[tid];
        sm[O_E0  + tid] = eb[tid];
    }
    __syncthreads();

    // ---- layer 1 ----
    qk_phase(sm, Wa1, Wa2);                        __syncthreads();
    att_phase(sm);                                 __syncthreads();
    gemm_phase<false>(sm, W1, O_B1, emb, out, b);  __syncthreads();
    // ---- layer 2 ----
    qk_phase(sm, Wa1, Wa2);                        __syncthreads();
    att_phase(sm);                                 __syncthreads();
    gemm_phase<true>(sm, W2, O_B2, emb, out, b);
}

extern "C" void kernel_launch(void* const* d_in, const int* in_sizes, int n_in,
                              void* d_out, int out_size) {
    const float* emb = (const float*)d_in[0];
    const float* Wa1 = (const float*)d_in[1];
    const float* ba1 = (const float*)d_in[2];
    const float* Wa2 = (const float*)d_in[3];
    const float* ba2 = (const float*)d_in[4];
    const float* W1  = (const float*)d_in[5];
    const float* b1  = (const float*)d_in[6];
    const float* W2  = (const float*)d_in[7];
    const float* b2  = (const float*)d_in[8];
    float* out = (float*)d_out;

    const size_t smem = SMEM_FLOATS * sizeof(float);   // 52480 B -> 4 CTAs/SM
    cudaFuncSetAttribute(att0_fused_kernel,
                         cudaFuncAttributeMaxDynamicSharedMemorySize, (int)smem);
    att0_fused_kernel<<<Bn, TPB, smem>>>(emb, Wa1, ba1, Wa2, ba2, W1, b1, W2, b2, out);
}

// round 6
// speedup vs baseline: 1.3837x; 1.3837x over previous
#include <cuda_runtime.h>

// ---------------------------------------------------------------------------
// Fully-fused 2-layer GAT attention. 512 CTAs x 256 threads, 4 CTAs/SM.
//   exp(leaky_relu(q+k)) = Fq * Ek * max(e^{0.99q}, e^{-0.99k}); Fq cancels.
//   X <- Ek*X;  ATT[i] = sum_j max(Hq,Gk)*EkX / sum_j max(Hq,Gk)*Ek
// GEMMs use k-pair-packed weights (prepacked to a __device__ global by a
// tiny first kernel): acc2 += x_pair (x) Wp[kp][c]  -- no scalar-dup MOVs.
// ---------------------------------------------------------------------------

#define TPB 256
typedef unsigned long long u64;

constexpr int Bn = 512, Nn = 50, Dn = 64;
constexpr int ASZ = Nn * Dn;                  // 3200
constexpr int EMB_STRIDE = (Nn + 1) * Dn;     // 3264

// shared layout (floats)
constexpr int O_X    = 0;          // x -> EkX1 -> av1 -> EkX2
constexpr int O_HQ   = ASZ;        // Hq -> ATT
constexpr int O_EKGK = 2 * ASZ;    // rows of 128: {ek0,ek1,gk0,gk1} per d-pair
constexpr int O_BA1  = 4 * ASZ;
constexpr int O_BA2  = O_BA1 + Dn;
constexpr int O_B1   = O_BA2 + Dn;
constexpr int O_B2   = O_B1 + Dn;
constexpr int O_E0   = O_B2 + Dn;
constexpr int SMEM_FLOATS = O_E0 + Dn;        // 13120 floats = 52480 B

// k-pair-packed weights: g_wp[m][kp][c] = (W_m[2kp][c], W_m[2kp+1][c])
__device__ __align__(16) u64 g_wp[4][32][64];

// ---- f32x2 helpers --------------------------------------------------------
__device__ __forceinline__ u64 pk2(float lo, float hi) {
    u64 r; asm("mov.b64 %0, {%1,%2};" : "=l"(r) : "f"(lo), "f"(hi)); return r;
}
__device__ __forceinline__ float lo32(u64 v) {
    float a, b; asm("mov.b64 {%0,%1}, %2;" : "=f"(a), "=f"(b) : "l"(v)); return a;
}
__device__ __forceinline__ float hi32(u64 v) {
    float a, b; asm("mov.b64 {%0,%1}, %2;" : "=f"(a), "=f"(b) : "l"(v)); return b;
}
__device__ __forceinline__ u64 fma2(u64 a, u64 b, u64 c) {
    u64 d; asm("fma.rn.f32x2 %0, %1, %2, %3;" : "=l"(d) : "l"(a), "l"(b), "l"(c)); return d;
}
__device__ __forceinline__ u64 mul2(u64 a, u64 b) {
    u64 d; asm("mul.rn.f32x2 %0, %1, %2;" : "=l"(d) : "l"(a), "l"(b)); return d;
}

// ---- prepack kernel: 4 matrices -> k-pair-interleaved u64 form --------------
__global__ void prepack_kernel(const float* __restrict__ Wa1,
                               const float* __restrict__ Wa2,
                               const float* __restrict__ W1,
                               const float* __restrict__ W2) {
    const int idx = blockIdx.x * blockDim.x + threadIdx.x;   // 0..8191
    const int m  = idx >> 11;
    const int r  = idx & 2047;
    const int kp = r >> 6;
    const int c  = r & 63;
    const float* W = (m == 0) ? Wa1 : (m == 1) ? Wa2 : (m == 2) ? W1 : W2;
    g_wp[m][kp][c] = pk2(W[(2 * kp) * Dn + c], W[(2 * kp + 1) * Dn + c]);
}

// ---- proj: res[r][0..1] = (X[row,:] @ W)[c0,c0+1] + bias, rows = w+8r -------
// acc2.lo accumulates even-k terms, acc2.hi odd-k; combined in epilogue.
__device__ __forceinline__ void proj7(const float* __restrict__ sm, int xofs,
                                      const u64* __restrict__ wp,
                                      const float* __restrict__ bias2,
                                      float res[7][2], int w, int lane) {
    u64 a0[7], a1[7];
#pragma unroll
    for (int r = 0; r < 7; ++r) { a0[r] = 0ull; a1[r] = 0ull; }
#pragma unroll 2
    for (int kq = 0; kq < 16; ++kq) {
        const ulonglong2 w0 = __ldg(reinterpret_cast<const ulonglong2*>(wp + (2 * kq) * Dn) + lane);
        const ulonglong2 w1 = __ldg(reinterpret_cast<const ulonglong2*>(wp + (2 * kq + 1) * Dn) + lane);
#pragma unroll
        for (int r = 0; r < 7; ++r) {
            const ulonglong2 xv = *reinterpret_cast<const ulonglong2*>(
                sm + xofs + (w + 8 * r) * Dn + 4 * kq);   // broadcast: (x0,x1),(x2,x3)
            a0[r] = fma2(xv.x, w0.x, a0[r]);
            a1[r] = fma2(xv.x, w0.y, a1[r]);
            a0[r] = fma2(xv.y, w1.x, a0[r]);
            a1[r] = fma2(xv.y, w1.y, a1[r]);
        }
    }
    const float b0 = bias2[0], b1 = bias2[1];
#pragma unroll
    for (int r = 0; r < 7; ++r) {
        res[r][0] = lo32(a0[r]) + hi32(a0[r]) + b0;
        res[r][1] = lo32(a1[r]) + hi32(a1[r]) + b1;
    }
}

// ---- qk: q=X@Wa1+ba1 -> HQ; k=X@Wa2+ba2 -> EK|GK; then X <- Ek*X -----------
__device__ __forceinline__ void qk_phase(float* sm) {
    const int tid = threadIdx.x, lane = tid & 31, w = tid >> 5;
    const int d2 = lane * 2;

    float q[7][2];
    proj7(sm, O_X, &g_wp[0][0][0], sm + O_BA1 + d2, q, w, lane);
#pragma unroll
    for (int r = 0; r < 7; ++r) {
        const int row = w + 8 * r;
        if (row < Nn)
            *reinterpret_cast<u64*>(sm + O_HQ + row * Dn + d2) =
                pk2(__expf(0.99f * q[r][0]), __expf(0.99f * q[r][1]));
    }

    float kk[7][2];
    proj7(sm, O_X, &g_wp[1][0][0], sm + O_BA2 + d2, kk, w, lane);
    u64 ekr[7];
#pragma unroll
    for (int r = 0; r < 7; ++r) {
        const int row = w + 8 * r;
        if (row < Nn) {
            const float e0 = __expf(kk[r][0]), e1 = __expf(kk[r][1]);
            ekr[r] = pk2(e0, e1);
            *reinterpret_cast<float4*>(sm + O_EKGK + row * 2 * Dn + d2 * 2) =
                make_float4(e0, e1, __expf(-0.99f * kk[r][0]), __expf(-0.99f * kk[r][1]));
        }
    }
    __syncwarp();   // rows warp-private: only intra-warp hazard on X
#pragma unroll
    for (int r = 0; r < 7; ++r) {
        const int row = w + 8 * r;
        if (row < Nn) {
            u64* px = reinterpret_cast<u64*>(sm + O_X + row * Dn + d2);
            *px = mul2(ekr[r], *px);   // X <- Ek * X
        }
    }
}

// ---- attention: ATT[i] = sum_j m*EkX / sum_j m*Ek, m = max(Hq_i, Gk_j) -----
__device__ __forceinline__ void att_phase(float* sm) {
    const int tid = threadIdx.x;
    const int d2 = (tid & 31) * 2;
    const int g = tid >> 5;

    float hq0[7], hq1[7];
    u64 num[7], den[7];
#pragma unroll
    for (int r = 0; r < 7; ++r) {
        const int i = g + 8 * r;
        const int ii = (i < Nn) ? i : (Nn - 1);
        const u64 h = *reinterpret_cast<const u64*>(sm + O_HQ + ii * Dn + d2);
        hq0[r] = lo32(h); hq1[r] = hi32(h);
        num[r] = 0ull; den[r] = 0ull;
    }
#pragma unroll 2
    for (int j = 0; j < Nn; ++j) {
        const ulonglong2 eg = *reinterpret_cast<const ulonglong2*>(
            sm + O_EKGK + j * 2 * Dn + d2 * 2);          // (ek0,ek1),(gk0,gk1)
        const float gk0 = lo32(eg.y), gk1 = hi32(eg.y);
        const u64 xw = *reinterpret_cast<const u64*>(sm + O_X + j * Dn + d2);
#pragma unroll
        for (int r = 0; r < 7; ++r) {
            const u64 m = pk2(fmaxf(hq0[r], gk0), fmaxf(hq1[r], gk1));
            den[r] = fma2(m, eg.x, den[r]);
            num[r] = fma2(m, xw, num[r]);
        }
    }
#pragma unroll
    for (int r = 0; r < 7; ++r) {
        const int i = g + 8 * r;
        if (i < Nn)
            *reinterpret_cast<u64*>(sm + O_HQ + i * Dn + d2) =
                pk2(__fdividef(lo32(num[r]), lo32(den[r])),
                    __fdividef(hi32(num[r]), hi32(den[r])));
    }
}

// ---- gemm: ATT @ W + b. FINAL=false -> X (av1). FINAL=true -> gmem out -----
template <bool FINAL>
__device__ __forceinline__ void gemm_phase(float* sm, const u64* __restrict__ wp,
                                           int bofs, const float* __restrict__ emb,
                                           float* __restrict__ out, int b) {
    const int tid = threadIdx.x, lane = tid & 31, w = tid >> 5;
    const int d2 = lane * 2;

    float res[7][2];
    proj7(sm, O_HQ, wp, sm + bofs + d2, res, w, lane);

#pragma unroll
    for (int r = 0; r < 7; ++r) {
        const int row = w + 8 * r;
        if (row < Nn) {
            if (!FINAL) {
                *reinterpret_cast<u64*>(sm + O_X + row * Dn + d2) =
                    pk2(res[r][0], res[r][1]);   // av1
            } else {
                const u64 ekx = *reinterpret_cast<const u64*>(sm + O_X + row * Dn + d2);
                const u64 ek  = *reinterpret_cast<const u64*>(sm + O_EKGK + row * 2 * Dn + d2 * 2);
                const float av0 = __fdividef(lo32(ekx), lo32(ek));   // av1 = EkX/Ek
                const float av1 = __fdividef(hi32(ekx), hi32(ek));
                const float e0a = sm[O_E0 + d2], e0b = sm[O_E0 + d2 + 1];
                const float2 ie = __ldg(reinterpret_cast<const float2*>(
                    emb + b * EMB_STRIDE + (row + 1) * Dn + d2));
                float r0 = res[r][0] + av0 + e0a * ie.x;
                float r1 = res[r][1] + av1 + e0b * ie.y;
                r0 = fmaxf(r0, 0.01f * r0);
                r1 = fmaxf(r1, 0.01f * r1);
                *reinterpret_cast<float2*>(out + b * ASZ + row * Dn + d2) =
                    make_float2(r0, r1);
            }
        }
    }
}

__global__ void __launch_bounds__(TPB, 4)
att0_fused_kernel(const float* __restrict__ emb,
                  const float* __restrict__ ba1, const float* __restrict__ ba2,
                  const float* __restrict__ b1,  const float* __restrict__ b2,
                  float* __restrict__ out) {
    extern __shared__ float sm[];
    const int b = blockIdx.x, tid = threadIdx.x;
    const float* __restrict__ eb = emb + b * EMB_STRIDE;

    for (int idx = tid; idx < ASZ / 4; idx += TPB)
        reinterpret_cast<float4*>(sm + O_X)[idx] =
            __ldg(reinterpret_cast<const float4*>(eb + Dn) + idx);
    if (tid < Dn) {
        sm[O_BA1 + tid] = ba1[tid];
        sm[O_BA2 + tid] = ba2[tid];
        sm[O_B1  + tid] = b1[tid];
        sm[O_B2  + tid] = b2[tid];
        sm[O_E0  + tid] = eb[tid];
    }
    __syncthreads();

    // ---- layer 1 ----
    qk_phase(sm);                                              __syncthreads();
    att_phase(sm);                                             __syncthreads();
    gemm_phase<false>(sm, &g_wp[2][0][0], O_B1, emb, out, b);  __syncthreads();
    // ---- layer 2 ----
    qk_phase(sm);                                              __syncthreads();
    att_phase(sm);                                             __syncthreads();
    gemm_phase<true>(sm, &g_wp[3][0][0], O_B2, emb, out, b);
}

extern "C" void kernel_launch(void* const* d_in, const int* in_sizes, int n_in,
                              void* d_out, int out_size) {
    const float* emb = (const float*)d_in[0];
    const float* Wa1 = (const float*)d_in[1];
    const float* ba1 = (const float*)d_in[2];
    const float* Wa2 = (const float*)d_in[3];
    const float* ba2 = (const float*)d_in[4];
    const float* W1  = (const float*)d_in[5];
    const float* b1  = (const float*)d_in[6];
    const float* W2  = (const float*)d_in[7];
    const float* b2  = (const float*)d_in[8];
    float* out = (float*)d_out;

    prepack_kernel<<<32, 256>>>(Wa1, Wa2, W1, W2);

    const size_t smem = SMEM_FLOATS * sizeof(float);   // 52480 B -> 4 CTAs/SM
    cudaFuncSetAttribute(att0_fused_kernel,
                         cudaFuncAttributeMaxDynamicSharedMemorySize, (int)smem);
    att0_fused_kernel<<<Bn, TPB, smem>>>(emb, ba1, ba2, b1, b2, out);
}

// round 7
// speedup vs baseline: 1.4586x; 1.0541x over previous
#include <cuda_runtime.h>

// ---------------------------------------------------------------------------
// Fully-fused 2-layer GAT attention. 512 CTAs x 256 threads, 4 CTAs/SM.
//   exp(leaky_relu(q+k)) = Fq * Ek * max(e^{0.99q}, e^{-0.99k}); Fq cancels.
//   X <- Ek*X;  ATT[i] = sum_j max(Hq,Gk)*EkX / sum_j max(Hq,Gk)*Ek
// R4 base + scalar-hoisted max in att + k-packed gemm weights + fewer
// barriers + folded exp2 constants.
// ---------------------------------------------------------------------------

#define TPB 256
typedef unsigned long long u64;

constexpr int Bn = 512, Nn = 50, Dn = 64;
constexpr int ASZ = Nn * Dn;                  // 3200
constexpr int EMB_STRIDE = (Nn + 1) * Dn;     // 3264

constexpr float L2E   = 1.4426950408889634f;  // log2(e)
constexpr float L2E99 = 0.99f * L2E;

// shared layout (floats)
constexpr int O_X    = 0;          // x -> EkX1 -> av1 -> EkX2
constexpr int O_HQ   = ASZ;        // Hq -> ATT
constexpr int O_EKGK = 2 * ASZ;    // rows of 128: {ek0,ek1,gk0,gk1} per d-pair
constexpr int O_BA1  = 4 * ASZ;
constexpr int O_BA2  = O_BA1 + Dn;
constexpr int O_B1   = O_BA2 + Dn;
constexpr int O_B2   = O_B1 + Dn;
constexpr int O_E0   = O_B2 + Dn;
constexpr int SMEM_FLOATS = O_E0 + Dn;        // 13120 floats = 52480 B

// k-pair-packed GEMM weights: g_wp[m][kp][c] = (W_m[2kp][c], W_m[2kp+1][c])
// m: 0=W1, 1=W2
__device__ __align__(16) u64 g_wp[2][32][64];

// ---- f32x2 helpers --------------------------------------------------------
__device__ __forceinline__ u64 pk2(float lo, float hi) {
    u64 r; asm("mov.b64 %0, {%1,%2};" : "=l"(r) : "f"(lo), "f"(hi)); return r;
}
__device__ __forceinline__ u64 dup2(float x) {
    u64 r; asm("mov.b64 %0, {%1,%1};" : "=l"(r) : "f"(x)); return r;
}
__device__ __forceinline__ float lo32(u64 v) {
    float a, b; asm("mov.b64 {%0,%1}, %2;" : "=f"(a), "=f"(b) : "l"(v)); return a;
}
__device__ __forceinline__ float hi32(u64 v) {
    float a, b; asm("mov.b64 {%0,%1}, %2;" : "=f"(a), "=f"(b) : "l"(v)); return b;
}
__device__ __forceinline__ u64 fma2(u64 a, u64 b, u64 c) {
    u64 d; asm("fma.rn.f32x2 %0, %1, %2, %3;" : "=l"(d) : "l"(a), "l"(b), "l"(c)); return d;
}
__device__ __forceinline__ u64 mul2(u64 a, u64 b) {
    u64 d; asm("mul.rn.f32x2 %0, %1, %2;" : "=l"(d) : "l"(a), "l"(b)); return d;
}

// ---- prepack: W1, W2 -> k-pair-interleaved u64 form -------------------------
__global__ void prepack_kernel(const float* __restrict__ W1,
                               const float* __restrict__ W2) {
    const int idx = blockIdx.x * blockDim.x + threadIdx.x;   // 0..4095
    const int m  = idx >> 11;
    const int r  = idx & 2047;
    const int kp = r >> 6;
    const int c  = r & 63;
    const float* W = (m == 0) ? W1 : W2;
    g_wp[m][kp][c] = pk2(W[(2 * kp) * Dn + c], W[(2 * kp + 1) * Dn + c]);
}

// ---- qk: q=X@Wa1+ba1, k=X@Wa2+ba2 -> HQ, EK|GK; then X <- Ek*X -------------
// Joint pass: single X read feeds both projections (R4 structure).
__device__ __forceinline__ void qk_phase(float* sm, const float* __restrict__ Wa1,
                                         const float* __restrict__ Wa2) {
    const int tid = threadIdx.x, lane = tid & 31, w = tid >> 5;
    const int d2 = lane * 2;

    u64 aq[7], ak[7];
    const u64 bq = *reinterpret_cast<const u64*>(sm + O_BA1 + d2);
    const u64 bk = *reinterpret_cast<const u64*>(sm + O_BA2 + d2);
#pragma unroll
    for (int r = 0; r < 7; ++r) { aq[r] = bq; ak[r] = bk; }

#pragma unroll 2
    for (int c0 = 0; c0 < Dn; c0 += 2) {
        u64 x2[7];
#pragma unroll
        for (int r = 0; r < 7; ++r)
            x2[r] = *reinterpret_cast<const u64*>(sm + O_X + (w + 8 * r) * Dn + c0);
#pragma unroll
        for (int u = 0; u < 2; ++u) {
            const u64 wa = __ldg(reinterpret_cast<const u64*>(Wa1 + (c0 + u) * Dn) + lane);
            const u64 wb = __ldg(reinterpret_cast<const u64*>(Wa2 + (c0 + u) * Dn) + lane);
#pragma unroll
            for (int r = 0; r < 7; ++r) {
                const u64 xx = dup2(u ? hi32(x2[r]) : lo32(x2[r]));
                aq[r] = fma2(xx, wa, aq[r]);
                ak[r] = fma2(xx, wb, ak[r]);
            }
        }
    }

    u64 ekr[7];
#pragma unroll
    for (int r = 0; r < 7; ++r) {
        const int row = w + 8 * r;
        if (row < Nn) {
            const float qa = lo32(aq[r]), qb = hi32(aq[r]);
            const float ka = lo32(ak[r]), kb = hi32(ak[r]);
            *reinterpret_cast<u64*>(sm + O_HQ + row * Dn + d2) =
                pk2(exp2f(qa * L2E99), exp2f(qb * L2E99));
            const float e0 = exp2f(ka * L2E), e1 = exp2f(kb * L2E);
            ekr[r] = pk2(e0, e1);
            *reinterpret_cast<float4*>(sm + O_EKGK + row * 2 * Dn + d2 * 2) =
                make_float4(e0, e1, exp2f(ka * -L2E99), exp2f(kb * -L2E99));
        }
    }
    __syncwarp();   // rows warp-private: only intra-warp hazard on X
#pragma unroll
    for (int r = 0; r < 7; ++r) {
        const int row = w + 8 * r;
        if (row < Nn) {
            u64* px = reinterpret_cast<u64*>(sm + O_X + row * Dn + d2);
            *px = mul2(ekr[r], *px);   // X <- Ek * X
        }
    }
}

// ---- attention: ATT[i] = sum_j m*EkX / sum_j m*Ek, m = max(Hq_i, Gk_j) -----
__device__ __forceinline__ void att_phase(float* sm) {
    const int tid = threadIdx.x;
    const int d2 = (tid & 31) * 2;
    const int g = tid >> 5;

    float hq0[7], hq1[7];
    u64 num[7], den[7];
#pragma unroll
    for (int r = 0; r < 7; ++r) {
        const int i = g + 8 * r;
        const int ii = (i < Nn) ? i : (Nn - 1);
        const u64 h = *reinterpret_cast<const u64*>(sm + O_HQ + ii * Dn + d2);
        hq0[r] = lo32(h); hq1[r] = hi32(h);
        num[r] = 0ull; den[r] = 0ull;
    }
#pragma unroll 2
    for (int j = 0; j < Nn; ++j) {
        const float4 eg = *reinterpret_cast<const float4*>(sm + O_EKGK + j * 2 * Dn + d2 * 2);
        const u64 ek = pk2(eg.x, eg.y);              // packed once per j
        const float gk0 = eg.z, gk1 = eg.w;          // scalars once per j
        const u64 xw = *reinterpret_cast<const u64*>(sm + O_X + j * Dn + d2);
#pragma unroll
        for (int r = 0; r < 7; ++r) {
            const u64 m = pk2(fmaxf(hq0[r], gk0), fmaxf(hq1[r], gk1));
            den[r] = fma2(m, ek, den[r]);
            num[r] = fma2(m, xw, num[r]);
        }
    }
#pragma unroll
    for (int r = 0; r < 7; ++r) {
        const int i = g + 8 * r;
        if (i < Nn)
            *reinterpret_cast<u64*>(sm + O_HQ + i * Dn + d2) =
                pk2(__fdividef(lo32(num[r]), lo32(den[r])),
                    __fdividef(hi32(num[r]), hi32(den[r])));
    }
}

// ---- gemm: ATT @ W + b (k-pair-packed weights). ----------------------------
// acc2.lo accumulates even-k terms, acc2.hi odd-k; folded in epilogue.
template <bool FINAL>
__device__ __forceinline__ void gemm_phase(float* sm, const u64* __restrict__ wp,
                                           int bofs, const float* __restrict__ emb,
                                           float* __restrict__ out, int b) {
    const int tid = threadIdx.x, lane = tid & 31, w = tid >> 5;
    const int d2 = lane * 2;

    u64 a0[7], a1[7];
#pragma unroll
    for (int r = 0; r < 7; ++r) { a0[r] = 0ull; a1[r] = 0ull; }
#pragma unroll 2
    for (int kq = 0; kq < 16; ++kq) {
        const ulonglong2 w0 = __ldg(reinterpret_cast<const ulonglong2*>(wp + (2 * kq) * Dn) + lane);
        const ulonglong2 w1 = __ldg(reinterpret_cast<const ulonglong2*>(wp + (2 * kq + 1) * Dn) + lane);
#pragma unroll
        for (int r = 0; r < 7; ++r) {
            const ulonglong2 xv = *reinterpret_cast<const ulonglong2*>(
                sm + O_HQ + (w + 8 * r) * Dn + 4 * kq);   // broadcast (x0,x1),(x2,x3)
            a0[r] = fma2(xv.x, w0.x, a0[r]);
            a1[r] = fma2(xv.x, w0.y, a1[r]);
            a0[r] = fma2(xv.y, w1.x, a0[r]);
            a1[r] = fma2(xv.y, w1.y, a1[r]);
        }
    }

    const float b0 = sm[bofs + d2], b1 = sm[bofs + d2 + 1];
#pragma unroll
    for (int r = 0; r < 7; ++r) {
        const int row = w + 8 * r;
        if (row < Nn) {
            const float t0 = lo32(a0[r]) + hi32(a0[r]) + b0;
            const float t1 = lo32(a1[r]) + hi32(a1[r]) + b1;
            if (!FINAL) {
                *reinterpret_cast<u64*>(sm + O_X + row * Dn + d2) = pk2(t0, t1);  // av1
            } else {
                const u64 ekx = *reinterpret_cast<const u64*>(sm + O_X + row * Dn + d2);
                const u64 ek  = *reinterpret_cast<const u64*>(sm + O_EKGK + row * 2 * Dn + d2 * 2);
                const float av0 = __fdividef(lo32(ekx), lo32(ek));   // av1 = EkX/Ek
                const float av1 = __fdividef(hi32(ekx), hi32(ek));
                const float e0a = sm[O_E0 + d2], e0b = sm[O_E0 + d2 + 1];
                const float2 ie = __ldg(reinterpret_cast<const float2*>(
                    emb + b * EMB_STRIDE + (row + 1) * Dn + d2));
                float r0 = t0 + av0 + e0a * ie.x;
                float r1 = t1 + av1 + e0b * ie.y;
                r0 = fmaxf(r0, 0.01f * r0);
                r1 = fmaxf(r1, 0.01f * r1);
                *reinterpret_cast<float2*>(out + b * ASZ + row * Dn + d2) =
                    make_float2(r0, r1);
            }
        }
    }
}

__global__ void __launch_bounds__(TPB, 4)
att0_fused_kernel(const float* __restrict__ emb,
                  const float* __restrict__ Wa1, const float* __restrict__ ba1,
                  const float* __restrict__ Wa2, const float* __restrict__ ba2,
                  const float* __restrict__ b1,  const float* __restrict__ b2,
                  float* __restrict__ out) {
    extern __shared__ float sm[];
    const int b = blockIdx.x, tid = threadIdx.x;
    const float* __restrict__ eb = emb + b * EMB_STRIDE;

    for (int idx = tid; idx < ASZ / 4; idx += TPB)
        reinterpret_cast<float4*>(sm + O_X)[idx] =
            __ldg(reinterpret_cast<const float4*>(eb + Dn) + idx);
    if (tid < Dn) {
        sm[O_BA1 + tid] = ba1[tid];
        sm[O_BA2 + tid] = ba2[tid];
        sm[O_B1  + tid] = b1[tid];
        sm[O_B2  + tid] = b2[tid];
        sm[O_E0  + tid] = eb[tid];
    }
    __syncthreads();

    // ---- layer 1 ----
    qk_phase(sm, Wa1, Wa2);                                    __syncthreads();
    att_phase(sm);                                             __syncthreads();
    gemm_phase<false>(sm, &g_wp[0][0][0], O_B1, emb, out, b);
    __syncwarp();   // gemm writes X[own rows]; qk2 reads X[own rows] cross-lane
    // ---- layer 2 (no CTA barrier needed: row ownership identical) ----
    qk_phase(sm, Wa1, Wa2);                                    __syncthreads();
    att_phase(sm);                                             __syncthreads();
    gemm_phase<true>(sm, &g_wp[1][0][0], O_B2, emb, out, b);
}

extern "C" void kernel_launch(void* const* d_in, const int* in_sizes, int n_in,
                              void* d_out, int out_size) {
    const float* emb = (const float*)d_in[0];
    const float* Wa1 = (const float*)d_in[1];
    const float* ba1 = (const float*)d_in[2];
    const float* Wa2 = (const float*)d_in[3];
    const float* ba2 = (const float*)d_in[4];
    const float* W1  = (const float*)d_in[5];
    const float* b1  = (const float*)d_in[6];
    const float* W2  = (const float*)d_in[7];
    const float* b2  = (const float*)d_in[8];
    float* out = (float*)d_out;

    prepack_kernel<<<16, 256>>>(W1, W2);

    const size_t smem = SMEM_FLOATS * sizeof(float);   // 52480 B -> 4 CTAs/SM
    cudaFuncSetAttribute(att0_fused_kernel,
                         cudaFuncAttributeMaxDynamicSharedMemorySize, (int)smem);
    att0_fused_kernel<<<Bn, TPB, smem>>>(emb, Wa1, ba1, Wa2, ba2, b1, b2, out);
}

// round 8
// speedup vs baseline: 1.4912x; 1.0224x over previous
#include <cuda_runtime.h>

// ---------------------------------------------------------------------------
// Fully-fused 2-layer GAT attention. 512 CTAs x 256 threads, 4 CTAs/SM.
//   exp(leaky_relu(q+k)) = Fq * Ek * max(e^{0.99q}, e^{-0.99k}); Fq cancels.
//   X <- Ek*X;  ATT[i] = sum_j max(Hq,Gk)*EkX / sum_j max(Hq,Gk)*Ek
// R7 base + exact-50 row split (warps 0-1: 7 rows, warps 2-7: 6 rows; no
// clamped duplicate work) + Hq carried in registers across qk->att (no HQ
// smem traffic) + prefetched final-epilogue globals.
// ---------------------------------------------------------------------------

#define TPB 256
typedef unsigned long long u64;

constexpr int Bn = 512, Nn = 50, Dn = 64;
constexpr int ASZ = Nn * Dn;                  // 3200
constexpr int EMB_STRIDE = (Nn + 1) * Dn;     // 3264

constexpr float L2E   = 1.4426950408889634f;  // log2(e)
constexpr float L2E99 = 0.99f * L2E;

// shared layout (floats)
constexpr int O_X    = 0;          // x -> EkX1 -> av1 -> EkX2
constexpr int O_ATT  = ASZ;        // attention output (was HQ region)
constexpr int O_EKGK = 2 * ASZ;    // rows of 128: {ek0,ek1,gk0,gk1} per d-pair
constexpr int O_BA1  = 4 * ASZ;
constexpr int O_BA2  = O_BA1 + Dn;
constexpr int O_B1   = O_BA2 + Dn;
constexpr int O_B2   = O_B1 + Dn;
constexpr int O_E0   = O_B2 + Dn;
constexpr int SMEM_FLOATS = O_E0 + Dn;        // 13120 floats = 52480 B

// k-pair-packed GEMM weights: g_wp[m][kp][c] = (W_m[2kp][c], W_m[2kp+1][c])
__device__ __align__(16) u64 g_wp[2][32][64];

// ---- f32x2 helpers --------------------------------------------------------
__device__ __forceinline__ u64 pk2(float lo, float hi) {
    u64 r; asm("mov.b64 %0, {%1,%2};" : "=l"(r) : "f"(lo), "f"(hi)); return r;
}
__device__ __forceinline__ u64 dup2(float x) {
    u64 r; asm("mov.b64 %0, {%1,%1};" : "=l"(r) : "f"(x)); return r;
}
__device__ __forceinline__ float lo32(u64 v) {
    float a, b; asm("mov.b64 {%0,%1}, %2;" : "=f"(a), "=f"(b) : "l"(v)); return a;
}
__device__ __forceinline__ float hi32(u64 v) {
    float a, b; asm("mov.b64 {%0,%1}, %2;" : "=f"(a), "=f"(b) : "l"(v)); return b;
}
__device__ __forceinline__ u64 fma2(u64 a, u64 b, u64 c) {
    u64 d; asm("fma.rn.f32x2 %0, %1, %2, %3;" : "=l"(d) : "l"(a), "l"(b), "l"(c)); return d;
}
__device__ __forceinline__ u64 mul2(u64 a, u64 b) {
    u64 d; asm("mul.rn.f32x2 %0, %1, %2;" : "=l"(d) : "l"(a), "l"(b)); return d;
}

// ---- prepack: W1, W2 -> k-pair-interleaved u64 form -------------------------
__global__ void prepack_kernel(const float* __restrict__ W1,
                               const float* __restrict__ W2) {
    const int idx = blockIdx.x * blockDim.x + threadIdx.x;   // 0..4095
    const int m  = idx >> 11;
    const int r  = idx & 2047;
    const int kp = r >> 6;
    const int c  = r & 63;
    const float* W = (m == 0) ? W1 : W2;
    g_wp[m][kp][c] = pk2(W[(2 * kp) * Dn + c], W[(2 * kp + 1) * Dn + c]);
}

// ---- qk (R rows): q,k projections -> hq regs, EK|GK smem; X <- Ek*X --------
template <int R>
__device__ __forceinline__ void qk_phase(float* sm, const float* __restrict__ Wa1,
                                         const float* __restrict__ Wa2,
                                         float* hq0, float* hq1, int w, int lane) {
    const int d2 = lane * 2;

    u64 aq[R], ak[R];
    const u64 bq = *reinterpret_cast<const u64*>(sm + O_BA1 + d2);
    const u64 bk = *reinterpret_cast<const u64*>(sm + O_BA2 + d2);
#pragma unroll
    for (int r = 0; r < R; ++r) { aq[r] = bq; ak[r] = bk; }

#pragma unroll 2
    for (int c0 = 0; c0 < Dn; c0 += 2) {
        u64 x2[R];
#pragma unroll
        for (int r = 0; r < R; ++r)
            x2[r] = *reinterpret_cast<const u64*>(sm + O_X + (w + 8 * r) * Dn + c0);
#pragma unroll
        for (int u = 0; u < 2; ++u) {
            const u64 wa = __ldg(reinterpret_cast<const u64*>(Wa1 + (c0 + u) * Dn) + lane);
            const u64 wb = __ldg(reinterpret_cast<const u64*>(Wa2 + (c0 + u) * Dn) + lane);
#pragma unroll
            for (int r = 0; r < R; ++r) {
                const u64 xx = dup2(u ? hi32(x2[r]) : lo32(x2[r]));
                aq[r] = fma2(xx, wa, aq[r]);
                ak[r] = fma2(xx, wb, ak[r]);
            }
        }
    }

    u64 ekr[R];
#pragma unroll
    for (int r = 0; r < R; ++r) {
        const int row = w + 8 * r;
        const float qa = lo32(aq[r]), qb = hi32(aq[r]);
        const float ka = lo32(ak[r]), kb = hi32(ak[r]);
        hq0[r] = exp2f(qa * L2E99);              // Hq stays in registers
        hq1[r] = exp2f(qb * L2E99);
        const float e0 = exp2f(ka * L2E), e1 = exp2f(kb * L2E);
        ekr[r] = pk2(e0, e1);
        *reinterpret_cast<float4*>(sm + O_EKGK + row * 2 * Dn + d2 * 2) =
            make_float4(e0, e1, exp2f(ka * -L2E99), exp2f(kb * -L2E99));
    }
    __syncwarp();   // rows warp-private: only intra-warp hazard on X
#pragma unroll
    for (int r = 0; r < R; ++r) {
        u64* px = reinterpret_cast<u64*>(sm + O_X + (w + 8 * r) * Dn + d2);
        *px = mul2(ekr[r], *px);   // X <- Ek * X
    }
}

// ---- attention (R rows): ATT[i] = sum_j m*EkX / sum_j m*Ek ------------------
template <int R>
__device__ __forceinline__ void att_phase(float* sm, const float* hq0,
                                          const float* hq1, int w, int lane) {
    const int d2 = lane * 2;

    u64 num[R], den[R];
#pragma unroll
    for (int r = 0; r < R; ++r) { num[r] = 0ull; den[r] = 0ull; }

#pragma unroll 2
    for (int j = 0; j < Nn; ++j) {
        const float4 eg = *reinterpret_cast<const float4*>(sm + O_EKGK + j * 2 * Dn + d2 * 2);
        const u64 ek = pk2(eg.x, eg.y);
        const float gk0 = eg.z, gk1 = eg.w;
        const u64 xw = *reinterpret_cast<const u64*>(sm + O_X + j * Dn + d2);
#pragma unroll
        for (int r = 0; r < R; ++r) {
            const u64 m = pk2(fmaxf(hq0[r], gk0), fmaxf(hq1[r], gk1));
            den[r] = fma2(m, ek, den[r]);
            num[r] = fma2(m, xw, num[r]);
        }
    }
#pragma unroll
    for (int r = 0; r < R; ++r) {
        *reinterpret_cast<u64*>(sm + O_ATT + (w + 8 * r) * Dn + d2) =
            pk2(__fdividef(lo32(num[r]), lo32(den[r])),
                __fdividef(hi32(num[r]), hi32(den[r])));
    }
}

// ---- gemm (R rows): ATT @ W + b (k-pair-packed weights) --------------------
template <int R, bool FINAL>
__device__ __forceinline__ void gemm_phase(float* sm, const u64* __restrict__ wp,
                                           int bofs, const float* __restrict__ emb,
                                           float* __restrict__ out, int b,
                                           int w, int lane) {
    const int d2 = lane * 2;

    // Prefetch final-epilogue globals before the FMA loop (overlap LDG).
    float ui0[FINAL ? R : 1], ui1[FINAL ? R : 1];
    if (FINAL) {
        const float e0a = sm[O_E0 + d2], e0b = sm[O_E0 + d2 + 1];
#pragma unroll
        for (int r = 0; r < R; ++r) {
            const float2 ie = __ldg(reinterpret_cast<const float2*>(
                emb + b * EMB_STRIDE + (w + 8 * r + 1) * Dn + d2));
            ui0[r] = e0a * ie.x;
            ui1[r] = e0b * ie.y;
        }
    }

    u64 a0[R], a1[R];
#pragma unroll
    for (int r = 0; r < R; ++r) { a0[r] = 0ull; a1[r] = 0ull; }
#pragma unroll 2
    for (int kq = 0; kq < 16; ++kq) {
        const ulonglong2 w0 = __ldg(reinterpret_cast<const ulonglong2*>(wp + (2 * kq) * Dn) + lane);
        const ulonglong2 w1 = __ldg(reinterpret_cast<const ulonglong2*>(wp + (2 * kq + 1) * Dn) + lane);
#pragma unroll
        for (int r = 0; r < R; ++r) {
            const ulonglong2 xv = *reinterpret_cast<const ulonglong2*>(
                sm + O_ATT + (w + 8 * r) * Dn + 4 * kq);   // (x0,x1),(x2,x3)
            a0[r] = fma2(xv.x, w0.x, a0[r]);
            a1[r] = fma2(xv.x, w0.y, a1[r]);
            a0[r] = fma2(xv.y, w1.x, a0[r]);
            a1[r] = fma2(xv.y, w1.y, a1[r]);
        }
    }

    const float b0 = sm[bofs + d2], b1 = sm[bofs + d2 + 1];
#pragma unroll
    for (int r = 0; r < R; ++r) {
        const int row = w + 8 * r;
        const float t0 = lo32(a0[r]) + hi32(a0[r]) + b0;
        const float t1 = lo32(a1[r]) + hi32(a1[r]) + b1;
        if (!FINAL) {
            *reinterpret_cast<u64*>(sm + O_X + row * Dn + d2) = pk2(t0, t1);  // av1
        } else {
            const u64 ekx = *reinterpret_cast<const u64*>(sm + O_X + row * Dn + d2);
            const u64 ek  = *reinterpret_cast<const u64*>(sm + O_EKGK + row * 2 * Dn + d2 * 2);
            const float av0 = __fdividef(lo32(ekx), lo32(ek));   // av1 = EkX/Ek
            const float av1 = __fdividef(hi32(ekx), hi32(ek));
            float r0 = t0 + av0 + ui0[r];
            float r1 = t1 + av1 + ui1[r];
            r0 = fmaxf(r0, 0.01f * r0);
            r1 = fmaxf(r1, 0.01f * r1);
            *reinterpret_cast<float2*>(out + b * ASZ + row * Dn + d2) =
                make_float2(r0, r1);
        }
    }
}

__global__ void __launch_bounds__(TPB, 4)
att0_fused_kernel(const float* __restrict__ emb,
                  const float* __restrict__ Wa1, const float* __restrict__ ba1,
                  const float* __restrict__ Wa2, const float* __restrict__ ba2,
                  const float* __restrict__ b1,  const float* __restrict__ b2,
                  float* __restrict__ out) {
    extern __shared__ float sm[];
    const int b = blockIdx.x, tid = threadIdx.x;
    const int lane = tid & 31, w = tid >> 5;
    const bool tall = (w < 2);        // warps 0,1 own 7 rows; warps 2-7 own 6
    const float* __restrict__ eb = emb + b * EMB_STRIDE;

    for (int idx = tid; idx < ASZ / 4; idx += TPB)
        reinterpret_cast<float4*>(sm + O_X)[idx] =
            __ldg(reinterpret_cast<const float4*>(eb + Dn) + idx);
    if (tid < Dn) {
        sm[O_BA1 + tid] = ba1[tid];
        sm[O_BA2 + tid] = ba2[tid];
        sm[O_B1  + tid] = b1[tid];
        sm[O_B2  + tid] = b2[tid];
        sm[O_E0  + tid] = eb[tid];
    }
    __syncthreads();

    float hq0[7], hq1[7];

    // ---- layer 1 ----
    if (tall) qk_phase<7>(sm, Wa1, Wa2, hq0, hq1, w, lane);
    else      qk_phase<6>(sm, Wa1, Wa2, hq0, hq1, w, lane);
    __syncthreads();
    if (tall) att_phase<7>(sm, hq0, hq1, w, lane);
    else      att_phase<6>(sm, hq0, hq1, w, lane);
    __syncthreads();
    if (tall) gemm_phase<7, false>(sm, &g_wp[0][0][0], O_B1, emb, out, b, w, lane);
    else      gemm_phase<6, false>(sm, &g_wp[0][0][0], O_B1, emb, out, b, w, lane);
    __syncwarp();   // gemm writes X[own rows]; qk2 reads X[own rows] cross-lane
    // ---- layer 2 ----
    if (tall) qk_phase<7>(sm, Wa1, Wa2, hq0, hq1, w, lane);
    else      qk_phase<6>(sm, Wa1, Wa2, hq0, hq1, w, lane);
    __syncthreads();
    if (tall) att_phase<7>(sm, hq0, hq1, w, lane);
    else      att_phase<6>(sm, hq0, hq1, w, lane);
    __syncthreads();
    if (tall) gemm_phase<7, true>(sm, &g_wp[1][0][0], O_B2, emb, out, b, w, lane);
    else      gemm_phase<6, true>(sm, &g_wp[1][0][0], O_B2, emb, out, b, w, lane);
}

extern "C" void kernel_launch(void* const* d_in, const int* in_sizes, int n_in,
                              void* d_out, int out_size) {
    const float* emb = (const float*)d_in[0];
    const float* Wa1 = (const float*)d_in[1];
    const float* ba1 = (const float*)d_in[2];
    const float* Wa2 = (const float*)d_in[3];
    const float* ba2 = (const float*)d_in[4];
    const float* W1  = (const float*)d_in[5];
    const float* b1  = (const float*)d_in[6];
    const float* W2  = (const float*)d_in[7];
    const float* b2  = (const float*)d_in[8];
    float* out = (float*)d_out;

    prepack_kernel<<<16, 256>>>(W1, W2);

    const size_t smem = SMEM_FLOATS * sizeof(float);   // 52480 B -> 4 CTAs/SM
    cudaFuncSetAttribute(att0_fused_kernel,
                         cudaFuncAttributeMaxDynamicSharedMemorySize, (int)smem);
    att0_fused_kernel<<<Bn, TPB, smem>>>(emb, Wa1, ba1, Wa2, ba2, b1, b2, out);
}